// round 5
// baseline (speedup 1.0000x reference)
#include <cuda_runtime.h>
#include <math.h>

// Top2Router: x[16384,2048] fp32, W[8,2048], b[8]
// out (fp32 concat): top2_val[N*2] | top2_idx[N*2] | gate[N*8]
//
// 1024 threads (32 warps, 50% occ), grid=#SMs, balanced token ranges.
// Warp = (token-half h, k-slice ws): h=w>>4 covers 64 tokens, ws=w&15 covers
// 4 k per chunk. 4-stage cp.async ring (KCHUNK=64, dist 2), 1 bar/chunk.
// XS_STRIDE=68 (16B-aligned rows + conflict-free phased LDS.128).
// f32x2 packed accumulation; ~55 regs/thread -> fits 8 warps/SMSP.

#define D_MODEL   2048
#define NEXP      8
#define NTOKMAX   128
#define KCHUNK    64
#define NCHUNK    (D_MODEL / KCHUNK)   // 32
#define XS_STRIDE 68
#define NSTAGE    4
#define THREADS   1024
#define NKW       16                   // k-slice warps per token-half
#define KSLICE    (KCHUNK / NKW)       // 4

typedef unsigned long long u64;

__device__ __forceinline__ void cp_async16(float* smem_dst, const float* gsrc) {
    unsigned saddr = (unsigned)__cvta_generic_to_shared(smem_dst);
    asm volatile("cp.async.cg.shared.global [%0], [%1], 16;\n"
                 :: "r"(saddr), "l"(gsrc));
}
#define CP_COMMIT() asm volatile("cp.async.commit_group;\n" ::: "memory")
#define CP_WAIT(n)  asm volatile("cp.async.wait_group %0;\n" :: "n"(n) : "memory")

__global__ __launch_bounds__(THREADS, 1)
void top2_router_kernel(const float* __restrict__ x,
                        const float* __restrict__ W,
                        const float* __restrict__ b,
                        float* __restrict__ out,
                        int n_tok)
{
    extern __shared__ float smem[];
    float* wt   = smem;                         // 2048*8 = 16384 floats (64KB)
    float* ring = wt + D_MODEL * NEXP;          // 4 * 128*68 = 34816 floats

    const int tid  = threadIdx.x;
    const int w    = tid >> 5;
    const int lane = tid & 31;
    const int h    = w >> 4;                    // token half: 0 or 1
    const int ws   = w & 15;                    // k-slice warp id

    // balanced token range (units of 8 tokens)
    const int G     = gridDim.x;
    const int units = n_tok >> 3;
    const int s8    = (int)(((long long)blockIdx.x       * units) / G);
    const int e8    = (int)(((long long)(blockIdx.x + 1) * units) / G);
    const int tokenBase = s8 * 8;
    const int ntok_b    = (e8 - s8) * 8;        // <= 112 for G >= 152

    // ---- stage W transposed: wt[k*8+e] = W[e*2048+k]
    #pragma unroll
    for (int i = 0; i < (D_MODEL * NEXP) / THREADS; ++i) {   // 16
        int idx = tid + i * THREADS;
        int e = idx >> 11;
        int k = idx & (D_MODEL - 1);
        wt[k * NEXP + e] = W[idx];
    }
    const u64* wt64 = reinterpret_cast<const u64*>(wt);

    // thread covers tokens h*64 + lane + t*32, t in {0,1}; 4 expert-pairs
    u64 acc[2][4];
    #pragma unroll
    for (int t = 0; t < 2; ++t)
        #pragma unroll
        for (int p = 0; p < 4; ++p) acc[t][p] = 0ull;

    const float* gx = x + (size_t)tokenBase * D_MODEL;

    // chunk tile: ntok_b x 64 floats = up to 2048 float4; 1024 thr -> 2 each
    #define PREFETCH(c_) do {                                              \
        float* dst = ring + ((c_) % NSTAGE) * (NTOKMAX * XS_STRIDE);       \
        const float* gsrc = gx + (c_) * KCHUNK;                            \
        _Pragma("unroll")                                                  \
        for (int i = 0; i < 2; ++i) {                                      \
            int idx = tid + i * THREADS;   /* 0..2047 float4 units */      \
            int t   = idx >> 4;            /* 16 float4 per row */         \
            int k4  = idx & 15;                                            \
            if (t < ntok_b)                                                \
                cp_async16(dst + t * XS_STRIDE + k4 * 4,                   \
                           gsrc + (size_t)t * D_MODEL + k4 * 4);           \
        }                                                                  \
        CP_COMMIT();                                                       \
    } while (0)

    PREFETCH(0); PREFETCH(1);

    const int tok0 = h * 64 + lane;             // first of this thread's 2 tokens
    const int kbase = ws * KSLICE;

    for (int c = 0; c < NCHUNK; ++c) {
        if (c + 2 < NCHUNK) { PREFETCH(c + 2); CP_WAIT(2); }
        else if (c + 1 < NCHUNK) CP_WAIT(1);
        else                     CP_WAIT(0);
        __syncthreads();

        const float* cur = ring + (c % NSTAGE) * (NTOKMAX * XS_STRIDE);

        float4 xv[2];
        #pragma unroll
        for (int t = 0; t < 2; ++t)
            xv[t] = *reinterpret_cast<const float4*>(
                cur + (tok0 + t * 32) * XS_STRIDE + kbase);

        #pragma unroll
        for (int j = 0; j < KSLICE; ++j) {
            int kg = c * KCHUNK + kbase + j;
            u64 wp0 = wt64[kg * 4 + 0];   // broadcast LDS.64
            u64 wp1 = wt64[kg * 4 + 1];
            u64 wp2 = wt64[kg * 4 + 2];
            u64 wp3 = wt64[kg * 4 + 3];
            #pragma unroll
            for (int t = 0; t < 2; ++t) {
                float xk = (j == 0) ? xv[t].x : (j == 1) ? xv[t].y
                         : (j == 2) ? xv[t].z : xv[t].w;
                u64 xx;
                asm("mov.b64 %0, {%1, %1};" : "=l"(xx) : "f"(xk));
                asm("fma.rn.f32x2 %0, %1, %2, %0;" : "+l"(acc[t][0]) : "l"(xx), "l"(wp0));
                asm("fma.rn.f32x2 %0, %1, %2, %0;" : "+l"(acc[t][1]) : "l"(xx), "l"(wp1));
                asm("fma.rn.f32x2 %0, %1, %2, %0;" : "+l"(acc[t][2]) : "l"(xx), "l"(wp2));
                asm("fma.rn.f32x2 %0, %1, %2, %0;" : "+l"(acc[t][3]) : "l"(xx), "l"(wp3));
            }
        }
    }
    __syncthreads();

    // ---- cross-warp reduction: 16 ws-partials per (token, pair)
    // red[(ws*128 + tok)*4 + p], tok global-in-block 0..127
    float2* red = reinterpret_cast<float2*>(ring);   // 16*128*4 float2 = 32768 floats
    #pragma unroll
    for (int t = 0; t < 2; ++t) {
        int tok = tok0 + t * 32;
        #pragma unroll
        for (int p = 0; p < 4; ++p) {
            float lo, hi;
            asm("mov.b64 {%0, %1}, %2;" : "=f"(lo), "=f"(hi) : "l"(acc[t][p]));
            red[(ws * NTOKMAX + tok) * 4 + p] = make_float2(lo, hi);
        }
    }
    __syncthreads();

    float* lgs = ring + NKW * NTOKMAX * 4 * 2;       // 128*8 floats
    if (tid < 512) {
        int tok = tid >> 2;                          // 0..127
        int p   = tid & 3;
        float2 s = make_float2(0.f, 0.f);
        #pragma unroll
        for (int ww = 0; ww < NKW; ++ww) {
            float2 v = red[(ww * NTOKMAX + tok) * 4 + p];
            s.x += v.x; s.y += v.y;
        }
        s.x += b[2 * p];
        s.y += b[2 * p + 1];
        reinterpret_cast<float2*>(lgs)[tok * 4 + p] = s;
    }
    __syncthreads();

    // ---- per-token softmax + stable top2
    if (tid < ntok_b) {
        const int g = tokenBase + tid;
        float gv[NEXP];
        float mx = -INFINITY;
        #pragma unroll
        for (int e = 0; e < NEXP; ++e) {
            gv[e] = lgs[tid * NEXP + e];
            mx = fmaxf(mx, gv[e]);
        }
        float ssum = 0.f;
        #pragma unroll
        for (int e = 0; e < NEXP; ++e) {
            gv[e] = __expf(gv[e] - mx);
            ssum += gv[e];
        }
        float inv = 1.f / ssum;
        #pragma unroll
        for (int e = 0; e < NEXP; ++e) gv[e] *= inv;

        float* gate_out = out + (size_t)n_tok * 4;
        float4 g0 = make_float4(gv[0], gv[1], gv[2], gv[3]);
        float4 g1 = make_float4(gv[4], gv[5], gv[6], gv[7]);
        *reinterpret_cast<float4*>(gate_out + (size_t)g * NEXP)     = g0;
        *reinterpret_cast<float4*>(gate_out + (size_t)g * NEXP + 4) = g1;

        int i1 = 0; float v1 = gv[0];
        #pragma unroll
        for (int e = 1; e < NEXP; ++e)
            if (gv[e] > v1) { v1 = gv[e]; i1 = e; }
        int i2 = -1; float v2 = -INFINITY;
        #pragma unroll
        for (int e = 0; e < NEXP; ++e)
            if (e != i1 && gv[e] > v2) { v2 = gv[e]; i2 = e; }

        out[(size_t)g * 2 + 0] = v1;
        out[(size_t)g * 2 + 1] = v2;
        float* idx_out = out + (size_t)n_tok * 2;
        idx_out[(size_t)g * 2 + 0] = (float)i1;
        idx_out[(size_t)g * 2 + 1] = (float)i2;
    }
}

extern "C" void kernel_launch(void* const* d_in, const int* in_sizes, int n_in,
                              void* d_out, int out_size)
{
    const float* x = (const float*)d_in[0];
    const float* W = (const float*)d_in[1];
    const float* b = (const float*)d_in[2];
    float* out = (float*)d_out;

    const int n_tok = in_sizes[0] / D_MODEL;    // 16384
    const int smem_bytes = (D_MODEL * NEXP + NSTAGE * NTOKMAX * XS_STRIDE)
                           * (int)sizeof(float);  // 204800 B

    static int nsm = 0;
    if (nsm == 0) {
        cudaDeviceProp prop;
        cudaGetDeviceProperties(&prop, 0);
        nsm = prop.multiProcessorCount;          // 152 on GB300
        cudaFuncSetAttribute(top2_router_kernel,
                             cudaFuncAttributeMaxDynamicSharedMemorySize, smem_bytes);
    }

    top2_router_kernel<<<nsm, THREADS, smem_bytes>>>(x, W, b, out, n_tok);
}